// round 10
// baseline (speedup 1.0000x reference)
#include <cuda_runtime.h>

#define NS 64      // states
#define NE 128     // edges = 2*NS
#define ROWS 4     // batch rows per warp
#define THREADS 512

// Fixed trellis structure (from the problem's _build_matrices):
//   src(e) = tflat[e] = 2*((e>>1)&31) + (e&1).
// mask is the 0/1 indicator of exactly this pattern, so
//   w[e] = sum_s s2e[s,e]*mask[s,e] = s2e[src(e),e]*mask[src(e),e].
// Values in s2e / l2e stay fully general (learnable).

__global__ void __launch_bounds__(THREADS)
acs_kernel(const float4* __restrict__ prob4,   // in_prob as [B*16] float4
           const float2* __restrict__ llrs2,   // llrs    as [B]    float2
           const float*  __restrict__ s2e,     // [64, 128]
           const float*  __restrict__ mask,    // [64, 128]
           const float*  __restrict__ l2e,     // [2, 128]
           float2* __restrict__ outm2,         // max as [B*32] float2
           float2* __restrict__ outi2,         // ind as [B*32] float2
           int batch)
{
    __shared__ __align__(16) float sh_w[NE];        // collapsed edge weights
    __shared__ __align__(16) float sh_c[2 * NE];    // l2e rows

    const int tid  = threadIdx.x;
    const int lane = tid & 31;

    // Stage per-edge constants once per block (coalesced).
    if (tid < NE) {
        const int e = tid;
        const int s = 2 * ((e >> 1) & 31) + (e & 1);   // src(e)
        sh_w[e] = s2e[s * NE + e] * mask[s * NE + e];
    }
    if (tid < 2 * NE)
        sh_c[tid] = l2e[tid];
    __syncthreads();

    const long long wid = (long long)blockIdx.x * (THREADS / 32) + (tid >> 5);
    const long long row0 = wid * ROWS;
    if (row0 >= batch) return;

    // Per-lane constants for edges 4l..4l+3 (conflict-free LDS.128).
    const float4 w4 = ((const float4*)sh_w)[lane];
    const float4 c0 = ((const float4*)sh_c)[lane];
    const float4 c1 = ((const float4*)(sh_c + NE))[lane];
    const int pidx = lane & 15;

    const int nr = (int)min((long long)ROWS, (long long)batch - row0);

    // Front-batched streaming loads (read-once -> evict-first).
    float4 p[ROWS];
    float2 L[ROWS];
    #pragma unroll
    for (int r = 0; r < ROWS; r++) {
        if (r < nr) {
            const long long row = row0 + r;
            p[r] = __ldcs(&prob4[row * 16 + pidx]);   // 16 unique float4/row
            L[r] = __ldcs(&llrs2[row]);               // warp-broadcast
        }
    }

    #pragma unroll
    for (int r = 0; r < ROWS; r++) {
        if (r >= nr) break;
        const long long row = row0 + r;

        // branch metrics for edges 4l..4l+3
        const float b0 = fmaf(L[r].x, c0.x, L[r].y * c1.x);
        const float b1 = fmaf(L[r].x, c0.y, L[r].y * c1.y);
        const float b2 = fmaf(L[r].x, c0.z, L[r].y * c1.z);
        const float b3 = fmaf(L[r].x, c0.w, L[r].y * c1.w);

        // path metrics
        const float x0 = fmaf(p[r].x, w4.x, b0);
        const float x1 = fmaf(p[r].y, w4.y, b1);
        const float x2 = fmaf(p[r].z, w4.z, b2);
        const float x3 = fmaf(p[r].w, w4.w, b3);

        float2 mx, id;
        mx.x = fmaxf(x0, x1); id.x = (x1 > x0) ? 1.0f : 0.0f;  // argmax tie -> 0
        mx.y = fmaxf(x2, x3); id.y = (x3 > x2) ? 1.0f : 0.0f;

        __stcs(&outm2[row * 32 + lane], mx);   // write-once: evict-first
        __stcs(&outi2[row * 32 + lane], id);
    }
}

extern "C" void kernel_launch(void* const* d_in, const int* in_sizes, int n_in,
                              void* d_out, int out_size) {
    const float* in_prob = (const float*)d_in[0];   // [B, 64]
    const float* llrs    = (const float*)d_in[1];   // [B, 2]
    const float* s2e     = (const float*)d_in[2];   // [64, 128]
    const float* mask    = (const float*)d_in[3];   // [64, 128]
    const float* l2e     = (const float*)d_in[4];   // [2, 128]

    const int batch = in_sizes[0] / NS;

    float* out_max = (float*)d_out;                          // [B, 64]
    float* out_ind = (float*)d_out + (long long)batch * NS;  // [B, 64]

    const long long warps = ((long long)batch + ROWS - 1) / ROWS;
    const int blocks = (int)((warps + (THREADS / 32) - 1) / (THREADS / 32));

    acs_kernel<<<blocks, THREADS>>>((const float4*)in_prob,
                                    (const float2*)llrs,
                                    s2e, mask, l2e,
                                    (float2*)out_max,
                                    (float2*)out_ind,
                                    batch);
}

// round 11
// speedup vs baseline: 1.0388x; 1.0388x over previous
#include <cuda_runtime.h>

#define NS 64      // states
#define NE 128     // edges = 2*NS
#define ROWS 4     // batch rows per warp
#define THREADS 256

// Fixed trellis structure (from the problem's _build_matrices):
//   src(e) = tflat[e] = 2*((e>>1)&31) + (e&1).
// mask is the 0/1 indicator of exactly this pattern, so
//   w[e] = sum_s s2e[s,e]*mask[s,e] = s2e[src(e),e]*mask[src(e),e].
// Values in s2e / l2e stay fully general (learnable).
//
// All hot-path indices fit in 32 bits: batch <= 2^19 here, and even at
// batch = 2^26 the largest element index (batch*32) stays < 2^31.

__global__ void __launch_bounds__(THREADS)
acs_kernel(const float4* __restrict__ prob4,   // in_prob as [B*16] float4
           const float2* __restrict__ llrs2,   // llrs    as [B]    float2
           const float*  __restrict__ s2e,     // [64, 128]
           const float*  __restrict__ mask,    // [64, 128]
           const float*  __restrict__ l2e,     // [2, 128]
           float2* __restrict__ outm2,         // max as [B*32] float2
           float2* __restrict__ outi2,         // ind as [B*32] float2
           int batch)
{
    __shared__ __align__(16) float sh_w[NE];        // collapsed edge weights
    __shared__ __align__(16) float sh_c[2 * NE];    // l2e rows

    const unsigned tid  = threadIdx.x;
    const unsigned lane = tid & 31u;

    // Stage per-edge constants once per block (coalesced).
    if (tid < NE) {
        const int e = (int)tid;
        const int s = 2 * ((e >> 1) & 31) + (e & 1);   // src(e)
        sh_w[e] = s2e[s * NE + e] * mask[s * NE + e];
    }
    sh_c[tid] = l2e[tid];                               // 256 == 2*NE
    __syncthreads();

    const unsigned wid  = blockIdx.x * (THREADS / 32u) + (tid >> 5);
    const unsigned row0 = wid * ROWS;
    if (row0 >= (unsigned)batch) return;

    // Per-lane constants for edges 4l..4l+3 (conflict-free LDS.128).
    const float4 w4 = ((const float4*)sh_w)[lane];
    const float4 c0 = ((const float4*)sh_c)[lane];
    const float4 c1 = ((const float4*)(sh_c + NE))[lane];
    const unsigned pidx = lane & 15u;

    const unsigned nr = min((unsigned)ROWS, (unsigned)batch - row0);

    // Front-batched streaming loads (read-once -> evict-first).
    float4 p[ROWS];
    float2 L[ROWS];
    #pragma unroll
    for (unsigned r = 0; r < ROWS; r++) {
        if (r < nr) {
            const unsigned row = row0 + r;
            p[r] = __ldcs(&prob4[row * 16u + pidx]);   // 16 unique float4/row
            L[r] = __ldcs(&llrs2[row]);                // warp-broadcast
        }
    }

    #pragma unroll
    for (unsigned r = 0; r < ROWS; r++) {
        if (r >= nr) break;
        const unsigned o = (row0 + r) * 32u + lane;

        // branch metrics for edges 4l..4l+3
        const float b0 = fmaf(L[r].x, c0.x, L[r].y * c1.x);
        const float b1 = fmaf(L[r].x, c0.y, L[r].y * c1.y);
        const float b2 = fmaf(L[r].x, c0.z, L[r].y * c1.z);
        const float b3 = fmaf(L[r].x, c0.w, L[r].y * c1.w);

        // path metrics
        const float x0 = fmaf(p[r].x, w4.x, b0);
        const float x1 = fmaf(p[r].y, w4.y, b1);
        const float x2 = fmaf(p[r].z, w4.z, b2);
        const float x3 = fmaf(p[r].w, w4.w, b3);

        float2 mx, id;
        mx.x = fmaxf(x0, x1); id.x = (x1 > x0) ? 1.0f : 0.0f;  // argmax tie -> 0
        mx.y = fmaxf(x2, x3); id.y = (x3 > x2) ? 1.0f : 0.0f;

        __stcs(&outm2[o], mx);   // write-once: evict-first
        __stcs(&outi2[o], id);
    }
}

extern "C" void kernel_launch(void* const* d_in, const int* in_sizes, int n_in,
                              void* d_out, int out_size) {
    const float* in_prob = (const float*)d_in[0];   // [B, 64]
    const float* llrs    = (const float*)d_in[1];   // [B, 2]
    const float* s2e     = (const float*)d_in[2];   // [64, 128]
    const float* mask    = (const float*)d_in[3];   // [64, 128]
    const float* l2e     = (const float*)d_in[4];   // [2, 128]

    const int batch = in_sizes[0] / NS;

    float* out_max = (float*)d_out;                          // [B, 64]
    float* out_ind = (float*)d_out + (long long)batch * NS;  // [B, 64]

    const long long warps = ((long long)batch + ROWS - 1) / ROWS;
    const int blocks = (int)((warps + (THREADS / 32) - 1) / (THREADS / 32));

    acs_kernel<<<blocks, THREADS>>>((const float4*)in_prob,
                                    (const float2*)llrs,
                                    s2e, mask, l2e,
                                    (float2*)out_max,
                                    (float2*)out_ind,
                                    batch);
}